// round 5
// baseline (speedup 1.0000x reference)
#include <cuda_runtime.h>
#include <cuda_bf16.h>
#include <cstdint>

#define N_ROWS   4194304
#define DIM      64
#define NUM_SEG  131072
#define ROWS_PER_BLOCK 256
#define LOCAL_SLOTS 1024

// ---------------- scratch (no allocations allowed) ----------------
__device__ float    g_segsum[NUM_SEG];
__device__ unsigned g_pend[N_ROWS / 32];   // per-warp pending-row bitmask

// ---------------- kernel 0: init (vectorized) ----------------
__global__ void k_init() {
    int i = blockIdx.x * blockDim.x + threadIdx.x;   // NUM_SEG/4 threads
    reinterpret_cast<float4*>(g_segsum)[i] = make_float4(0.f, 0.f, 0.f, 0.f);
}

// ---------------- kernel 1: fused GEMV + exp + block-local softmax ----------
// 16 lanes per row (one float4 each); warp covers 512B contiguous per LDG.128.
// Head lanes (0,16) own 16 consecutive rows each. Block = 256 consecutive rows.
// Segments fully inside the block are normalized here via smem sums; boundary
// segments get run-merged global atomicAdds and rows flagged in g_pend.
__global__ void __launch_bounds__(256) k_main(
    const float* __restrict__ X,
    const int*   __restrict__ seg,
    const float* __restrict__ W,
    const float* __restrict__ b,
    float*       __restrict__ out)
{
    __shared__ float sSum[LOCAL_SLOTS];
    __shared__ int   sMeta[3];   // segPrev, segNext, s0

    const int tid       = threadIdx.x;
    const int lane      = tid & 31;
    const int col       = lane & 15;
    const int half      = lane >> 4;
    const int warpInBlk = tid >> 5;
    const int B         = blockIdx.x * ROWS_PER_BLOCK;
    const int rowBase   = B + warpInBlk * 32;
    const int myRow0    = rowBase + 16 * half;

    // zero local sum table + load boundary metadata
#pragma unroll
    for (int q = 0; q < LOCAL_SLOTS / 256; ++q)
        sSum[tid + q * 256] = 0.0f;
    if (tid == 0) {
        sMeta[0] = (B > 0) ? __ldg(&seg[B - 1]) : -1;
        sMeta[1] = (B + ROWS_PER_BLOCK < N_ROWS) ? __ldg(&seg[B + ROWS_PER_BLOCK]) : 0x7fffffff;
        sMeta[2] = __ldg(&seg[B]);
    }

    const float w0 = __ldg(&W[col * 4 + 0]);
    const float w1 = __ldg(&W[col * 4 + 1]);
    const float w2 = __ldg(&W[col * 4 + 2]);
    const float w3 = __ldg(&W[col * 4 + 3]);
    const float b0 = __ldg(&b[0]);

    const float4* __restrict__ Xv = reinterpret_cast<const float4*>(X);
    const size_t base = (size_t)myRow0 * (DIM / 4) + col;
    const bool isHead = (col == 0);

    // head lanes preload their 16 seg ids
    int sid[16];
    if (isHead) {
        const int4* s4 = reinterpret_cast<const int4*>(seg + myRow0);
#pragma unroll
        for (int q = 0; q < 4; ++q) {
            int4 v = __ldg(&s4[q]);
            sid[4 * q + 0] = v.x; sid[4 * q + 1] = v.y;
            sid[4 * q + 2] = v.z; sid[4 * q + 3] = v.w;
        }
    }

    float e[16];
#pragma unroll
    for (int ii = 0; ii < 16; ii += 8) {
        float4 xs[8];
#pragma unroll
        for (int u = 0; u < 8; ++u)
            xs[u] = __ldg(&Xv[base + (size_t)(ii + u) * (DIM / 4)]);

#pragma unroll
        for (int u = 0; u < 8; ++u) {
            float a = xs[u].x * w0 + xs[u].y * w1 + xs[u].z * w2 + xs[u].w * w3;
#pragma unroll
            for (int d = 8; d >= 1; d >>= 1)
                a += __shfl_xor_sync(0xffffffffu, a, d);
            e[ii + u] = a;   // butterfly: all lanes hold row sum
        }
    }
    __syncthreads();   // sSum zeroed + sMeta visible

    const int segPrev = sMeta[0];
    const int segNext = sMeta[1];
    const int s0      = sMeta[2];

    unsigned pendMask = 0;   // ALL lanes init (needed by full-warp shuffle below)
    if (isHead) {
#pragma unroll
        for (int u = 0; u < 16; ++u)
            e[u] = __expf(e[u] + b0);

        // run-length-merged sums; route to smem (contained) / global (boundary)
        int   runSeg   = sid[0];
        float runSum   = e[0];
        int   runStart = 0;
#pragma unroll
        for (int u = 1; u <= 16; ++u) {
            int s = (u < 16) ? sid[u] : -2;   // force flush at end
            if (s == runSeg) { runSum += e[u]; continue; }
            int  slot = runSeg - s0;
            bool glob = (runSeg == segPrev) | (runSeg == segNext) | (slot >= LOCAL_SLOTS);
            if (glob) {
                atomicAdd(&g_segsum[runSeg], runSum);
                for (int r = runStart; r < u; ++r) pendMask |= (1u << r);
            } else {
                atomicAdd(&sSum[slot], runSum);
            }
            runSeg = s; runSum = (u < 16) ? e[u] : 0.0f; runStart = u;
        }
    }
    __syncthreads();   // smem sums complete

    if (isHead) {
        // normalize contained rows with block-local sums
        float r[16];
        int   curSeg = -1;
        float inv    = 1.0f;
#pragma unroll
        for (int u = 0; u < 16; ++u) {
            if (pendMask & (1u << u)) {
                r[u] = e[u];                      // fixup kernel finishes this
            } else {
                int s = sid[u];
                if (s != curSeg) { curSeg = s; inv = __frcp_rn(sSum[s - s0]); }
                r[u] = e[u] * inv;
            }
        }
        float4* ov = reinterpret_cast<float4*>(out + myRow0);
#pragma unroll
        for (int q = 0; q < 4; ++q)
            ov[q] = make_float4(r[4 * q], r[4 * q + 1], r[4 * q + 2], r[4 * q + 3]);
    }

    // combine the two halves' pending masks -> one uint per warp (32 rows).
    // Executed by ALL lanes with the full mask (lane0 <- lane16); non-head
    // lanes carry pendMask == 0.
    unsigned hi = __shfl_down_sync(0xffffffffu, pendMask, 16);
    if (lane == 0)
        g_pend[(unsigned)(rowBase >> 5)] = (pendMask & 0xffffu) | (hi << 16);
}

// ---------------- kernel 2: fixup for boundary-segment rows ----------------
__global__ void __launch_bounds__(256) k_fix(
    const int* __restrict__ seg,
    float*     __restrict__ out)
{
    int t = blockIdx.x * blockDim.x + threadIdx.x;
    int warpIdx = t >> 5;
    int lane    = t & 31;
    unsigned m  = g_pend[warpIdx];   // broadcast load (same addr per warp)
    if (m & (1u << lane)) {
        int row = warpIdx * 32 + lane;
        int s   = __ldg(&seg[row]);
        out[row] *= __frcp_rn(g_segsum[s]);
    }
}

// ---------------- launch ----------------
extern "C" void kernel_launch(void* const* d_in, const int* in_sizes, int n_in,
                              void* d_out, int out_size)
{
    const float* X   = (const float*)d_in[0];
    const int*   seg = (const int*)  d_in[1];
    const float* W   = (const float*)d_in[2];
    const float* b   = (const float*)d_in[3];
    float* out = (float*)d_out;

    k_init<<<NUM_SEG / 4 / 256, 256>>>();
    k_main<<<N_ROWS / ROWS_PER_BLOCK, 256>>>(X, seg, W, b, out);
    k_fix<<<N_ROWS / 256, 256>>>(seg, out);
}

// round 6
// speedup vs baseline: 1.4467x; 1.4467x over previous
#include <cuda_runtime.h>
#include <cuda_bf16.h>
#include <cstdint>

#define N_ROWS   4194304
#define DIM      64
#define NUM_SEG  131072

// ---------------- scratch (no allocations allowed) ----------------
__device__ float g_segsum[NUM_SEG];

// ---------------- kernel 0: init ----------------
__global__ void k_init() {
    int i = blockIdx.x * blockDim.x + threadIdx.x;   // NUM_SEG/4 threads
    reinterpret_cast<float4*>(g_segsum)[i] = make_float4(0.f, 0.f, 0.f, 0.f);
}

// ---------------- kernel 1: fused GEMV + exp + segment sum (R3 proven) -----
// 16 lanes per row (one float4 each); a warp covers 512B contiguous per
// LDG.128 -> 4 lines/instr. Head lanes (0,16) own 16 consecutive rows each
// and run-length-merge atomicAdds into g_segsum (seg sorted).
// X is streamed with __ldcs (evict-first) so out/seg stay resident in L2
// for k_norm.
__global__ void __launch_bounds__(256) k_main(
    const float* __restrict__ X,
    const int*   __restrict__ seg,
    const float* __restrict__ W,
    const float* __restrict__ b,
    float*       __restrict__ out)
{
    const int lane   = threadIdx.x & 31;
    const int col    = lane & 15;          // float4 index within row
    const int half   = lane >> 4;
    const int warpId = (blockIdx.x * blockDim.x + threadIdx.x) >> 5;
    const int rowBase = warpId * 32;       // 32 rows per warp
    const int myRow0  = rowBase + 16 * half;

    const float w0 = __ldg(&W[col * 4 + 0]);
    const float w1 = __ldg(&W[col * 4 + 1]);
    const float w2 = __ldg(&W[col * 4 + 2]);
    const float w3 = __ldg(&W[col * 4 + 3]);
    const float b0 = __ldg(&b[0]);

    const float4* __restrict__ Xv = reinterpret_cast<const float4*>(X);
    const size_t base = (size_t)myRow0 * (DIM / 4) + col;

    const bool isHead = (col == 0);

    // head lanes preload their 16 seg ids (aligned int4 x4)
    int sid[16];
    if (isHead) {
        const int4* s4 = reinterpret_cast<const int4*>(seg + myRow0);
#pragma unroll
        for (int q = 0; q < 4; ++q) {
            int4 v = __ldg(&s4[q]);
            sid[4 * q + 0] = v.x; sid[4 * q + 1] = v.y;
            sid[4 * q + 2] = v.z; sid[4 * q + 3] = v.w;
        }
    }

    int   curSeg = -1;
    float curAcc = 0.0f;

#pragma unroll
    for (int ii = 0; ii < 16; ii += 8) {
        float4 xs[8];
#pragma unroll
        for (int u = 0; u < 8; ++u)
            xs[u] = __ldcs(&Xv[base + (size_t)(ii + u) * (DIM / 4)]);

        float accs[8];
#pragma unroll
        for (int u = 0; u < 8; ++u) {
            float a = xs[u].x * w0 + xs[u].y * w1 + xs[u].z * w2 + xs[u].w * w3;
#pragma unroll
            for (int d = 8; d >= 1; d >>= 1)
                a += __shfl_xor_sync(0xffffffffu, a, d);
            accs[u] = a;
        }

        if (isHead) {
            float e[8];
#pragma unroll
            for (int u = 0; u < 8; ++u)
                e[u] = __expf(accs[u] + b0);

            float4* ov = reinterpret_cast<float4*>(out + myRow0 + ii);
            ov[0] = make_float4(e[0], e[1], e[2], e[3]);
            ov[1] = make_float4(e[4], e[5], e[6], e[7]);

            // run-length-merged segment sums
#pragma unroll
            for (int u = 0; u < 8; ++u) {
                int s = sid[ii + u];
                if (s != curSeg) {
                    if (curSeg >= 0) atomicAdd(&g_segsum[curSeg], curAcc);
                    curSeg = s;
                    curAcc = e[u];
                } else {
                    curAcc += e[u];
                }
            }
        }
    }
    if (isHead && curSeg >= 0) atomicAdd(&g_segsum[curSeg], curAcc);
}

// ---------------- kernel 2: normalize (8 rows / thread) ----------------
__global__ void __launch_bounds__(256) k_norm(
    const int* __restrict__ seg,
    float*     __restrict__ out)
{
    int t = blockIdx.x * blockDim.x + threadIdx.x;   // rows 8t..8t+7

    const int4*   sv = reinterpret_cast<const int4*>(seg) + 2 * t;
    float4*       ov = reinterpret_cast<float4*>(out) + 2 * t;

    int4   sa = __ldg(&sv[0]);
    int4   sb = __ldg(&sv[1]);
    float4 va = ov[0];
    float4 vb = ov[1];

    int s[8] = { sa.x, sa.y, sa.z, sa.w, sb.x, sb.y, sb.z, sb.w };
    float v[8] = { va.x, va.y, va.z, va.w, vb.x, vb.y, vb.z, vb.w };

    int   cur = s[0];
    float inv = __frcp_rn(g_segsum[cur]);
#pragma unroll
    for (int u = 0; u < 8; ++u) {
        if (s[u] != cur) { cur = s[u]; inv = __frcp_rn(g_segsum[cur]); }
        v[u] *= inv;
    }

    ov[0] = make_float4(v[0], v[1], v[2], v[3]);
    ov[1] = make_float4(v[4], v[5], v[6], v[7]);
}

// ---------------- launch ----------------
extern "C" void kernel_launch(void* const* d_in, const int* in_sizes, int n_in,
                              void* d_out, int out_size)
{
    const float* X   = (const float*)d_in[0];
    const int*   seg = (const int*)  d_in[1];
    const float* W   = (const float*)d_in[2];
    const float* b   = (const float*)d_in[3];
    float* out = (float*)d_out;

    k_init<<<NUM_SEG / 4 / 256, 256>>>();
    k_main<<<N_ROWS / 256, 256>>>(X, seg, W, b, out);
    k_norm<<<N_ROWS / 8 / 256, 256>>>(seg, out);
}